// round 10
// baseline (speedup 1.0000x reference)
#include <cuda_runtime.h>
#include <cstdint>

// TextEmbedding: gather [B,S,W,D] from table, per-token LayerNorm, sum over W.
// B=32, S=128, W=32, D=256  -> out [B*S, D] f32.
//
// R10: cp.async 4-stage ring (distance 3), 2 words/chunk, WPB=2.
// MIO diet vs R9: no id shuffles (per-lane __ldg of L1-resident ids; lanes
// 0-15 copy word A's row, 16-31 word B's), reduction tail uses 2 xor16
// exchanges instead of mtot-xor + 2 broadcast shfls: 9 shfl/chunk (was 12).

#define DIM 256
#define WORDS 32
#define EPS 1e-12f
#define STAGES 4
#define NCHUNK 16           // 2 words per chunk
#define WPB 2               // warps per block

typedef unsigned long long u64;

__device__ __forceinline__ u64 pack2(float lo, float hi) {
    u64 r; asm("mov.b64 %0, {%1, %2};" : "=l"(r) : "f"(lo), "f"(hi)); return r;
}
__device__ __forceinline__ void unpack2(u64 v, float& lo, float& hi) {
    asm("mov.b64 {%0, %1}, %2;" : "=f"(lo), "=f"(hi) : "l"(v));
}
__device__ __forceinline__ u64 add2(u64 a, u64 b) {
    u64 d; asm("add.rn.f32x2 %0, %1, %2;" : "=l"(d) : "l"(a), "l"(b)); return d;
}
__device__ __forceinline__ u64 mul2(u64 a, u64 b) {
    u64 d; asm("mul.rn.f32x2 %0, %1, %2;" : "=l"(d) : "l"(a), "l"(b)); return d;
}
__device__ __forceinline__ u64 fma2(u64 a, u64 b, u64 c) {
    u64 d; asm("fma.rn.f32x2 %0, %1, %2, %3;" : "=l"(d) : "l"(a), "l"(b), "l"(c)); return d;
}

__device__ __forceinline__ void cp16(uint32_t dst_smem, const void* src) {
    asm volatile("cp.async.cg.shared.global [%0], [%1], 16;"
                 :: "r"(dst_smem), "l"(src));
}
__device__ __forceinline__ void cp_commit() {
    asm volatile("cp.async.commit_group;");
}
template <int N> __device__ __forceinline__ void cp_wait() {
    asm volatile("cp.async.wait_group %0;" :: "n"(N));
}

__global__ __launch_bounds__(64)
void emb_ln_sum_kernel(const int* __restrict__ ids,
                       const float* __restrict__ table,
                       const float* __restrict__ gamma,
                       const float* __restrict__ beta,
                       float* __restrict__ out) {
    // [warp][stage][slot][lane]; stage = 2KB holding 2 rows in dim order.
    __shared__ float4 buf[WPB][STAGES][4][32];

    const int tid  = threadIdx.x;
    const int warp = tid >> 5;
    const int lane = tid & 31;
    const int pos  = blockIdx.x * WPB + warp;   // 0..4095

    const int* idp = ids + pos * WORDS;

    const uint32_t sbase0 =
        (uint32_t)__cvta_generic_to_shared(&buf[warp][0][0][0]);
    const uint32_t half_off = (uint32_t)(lane & 16) << 6;   // 0 or 1024
    const uint32_t lane_off = 64u * (lane & 15);

    // Producer: chunk c = words 2c (lanes 0-15) and 2c+1 (lanes 16-31).
    // Each lane copies 64B of its word's row; per-lane id via L1-hit LDG.
    auto issue = [&](int c) {
        const int w  = 2 * c + (lane >> 4);
        const int id = __ldg(idp + w);
        const float* src = table + (size_t)id * DIM + 16 * (lane & 15);
        const uint32_t dst = sbase0 + (uint32_t)(c & (STAGES - 1)) * 2048u
                           + half_off + lane_off;
        cp16(dst,      src);
        cp16(dst + 16, src + 4);
        cp16(dst + 32, src + 8);
        cp16(dst + 48, src + 12);
        cp_commit();
    };

    u64 acc[4];
    const u64 z = pack2(0.0f, 0.0f);
    acc[0] = z; acc[1] = z; acc[2] = z; acc[3] = z;
    float mtot = 0.0f;

    issue(0); issue(1); issue(2);

    #pragma unroll
    for (int c = 0; c < NCHUNK; c++) {
        if (c + 3 < NCHUNK) { issue(c + 3); cp_wait<3>(); }
        else if (c + 2 < NCHUNK) cp_wait<2>();
        else if (c + 1 < NCHUNK) cp_wait<1>();
        else                     cp_wait<0>();

        // Consumer lane reads its own dims back (conflict-free LDS.128).
        const float4* sp = &buf[warp][c & (STAGES - 1)][0][lane];
        const float4 R0 = sp[0];    // word0 dims [4L, 4L+4)
        const float4 R1 = sp[32];   // word0 dims [128+4L, ...)
        const float4 R2 = sp[64];   // word1 low
        const float4 R3 = sp[96];   // word1 high

        // Per-lane partials: v = {s0, q0, s1, q1}
        float v[4];
        {
            const u64 a01 = pack2(R0.x, R0.y), a23 = pack2(R0.z, R0.w);
            const u64 b01 = pack2(R1.x, R1.y), b23 = pack2(R1.z, R1.w);
            const u64 s2 = add2(add2(a01, a23), add2(b01, b23));
            const u64 q2 = fma2(a01, a01, fma2(a23, a23, fma2(b01, b01, mul2(b23, b23))));
            float sl, sh, ql, qh;
            unpack2(s2, sl, sh); unpack2(q2, ql, qh);
            v[0] = sl + sh; v[1] = ql + qh;
        }
        {
            const u64 a01 = pack2(R2.x, R2.y), a23 = pack2(R2.z, R2.w);
            const u64 b01 = pack2(R3.x, R3.y), b23 = pack2(R3.z, R3.w);
            const u64 s2 = add2(add2(a01, a23), add2(b01, b23));
            const u64 q2 = fma2(a01, a01, fma2(a23, a23, fma2(b01, b01, mul2(b23, b23))));
            float sl, sh, ql, qh;
            unpack2(s2, sl, sh); unpack2(q2, ql, qh);
            v[2] = sl + sh; v[3] = ql + qh;
        }

        // Fold: bit16 selects word, bit8 selects s/q; butterfly 4,2,1.
        const bool hi16 = (lane & 16) != 0;
        float w2[2];
        #pragma unroll
        for (int j = 0; j < 2; j++) {
            float send = hi16 ? v[j] : v[j + 2];
            float keep = hi16 ? v[j + 2] : v[j];
            w2[j] = keep + __shfl_xor_sync(0xffffffffu, send, 16);
        }
        const bool hi8 = (lane & 8) != 0;
        float y;
        {
            float send = hi8 ? w2[0] : w2[1];
            float keep = hi8 ? w2[1] : w2[0];
            y = keep + __shfl_xor_sync(0xffffffffu, send, 8);
        }
        y += __shfl_xor_sync(0xffffffffu, y, 4);
        y += __shfl_xor_sync(0xffffffffu, y, 2);
        y += __shfl_xor_sync(0xffffffffu, y, 1);
        // Lane holds: (s or q, by b8) of word b16.

        const float p  = __shfl_xor_sync(0xffffffffu, y, 8);
        const float s_ = hi8 ? p : y;
        const float q_ = hi8 ? y : p;
        const float mu  = s_ * (1.0f / 256.0f);
        const float var = q_ * (1.0f / 256.0f) - mu * mu;
        const float r_  = rsqrtf(var + EPS);
        const float msh = -mu * r_;

        // Exchange (rstd, msh) with the other word's lanes.
        const float r_o   = __shfl_xor_sync(0xffffffffu, r_, 16);
        const float msh_o = __shfl_xor_sync(0xffffffffu, msh, 16);
        mtot += msh + msh_o;
        const float r0 = hi16 ? r_o : r_;
        const float r1 = hi16 ? r_ : r_o;

        const u64 rr0 = pack2(r0, r0);
        const u64 rr1 = pack2(r1, r1);
        acc[0] = fma2(pack2(R0.x, R0.y), rr0, acc[0]);
        acc[1] = fma2(pack2(R0.z, R0.w), rr0, acc[1]);
        acc[2] = fma2(pack2(R1.x, R1.y), rr0, acc[2]);
        acc[3] = fma2(pack2(R1.z, R1.w), rr0, acc[3]);
        acc[0] = fma2(pack2(R2.x, R2.y), rr1, acc[0]);
        acc[1] = fma2(pack2(R2.z, R2.w), rr1, acc[1]);
        acc[2] = fma2(pack2(R3.x, R3.y), rr1, acc[2]);
        acc[3] = fma2(pack2(R3.z, R3.w), rr1, acc[3]);
    }

    // out = (acc + mtot) * gamma + 32 * beta, per lane dims.
    float a0, a1, a2, a3, a4, a5, a6, a7;
    unpack2(acc[0], a0, a1); unpack2(acc[1], a2, a3);
    unpack2(acc[2], a4, a5); unpack2(acc[3], a6, a7);

    const float4 g0  = __ldg((const float4*)gamma + lane);
    const float4 g1  = __ldg((const float4*)gamma + 32 + lane);
    const float4 bt0 = __ldg((const float4*)beta + lane);
    const float4 bt1 = __ldg((const float4*)beta + 32 + lane);

    float4 o0, o1;
    o0.x = fmaf(a0 + mtot, g0.x, 32.0f * bt0.x);
    o0.y = fmaf(a1 + mtot, g0.y, 32.0f * bt0.y);
    o0.z = fmaf(a2 + mtot, g0.z, 32.0f * bt0.z);
    o0.w = fmaf(a3 + mtot, g0.w, 32.0f * bt0.w);
    o1.x = fmaf(a4 + mtot, g1.x, 32.0f * bt1.x);
    o1.y = fmaf(a5 + mtot, g1.y, 32.0f * bt1.y);
    o1.z = fmaf(a6 + mtot, g1.z, 32.0f * bt1.z);
    o1.w = fmaf(a7 + mtot, g1.w, 32.0f * bt1.w);

    float4* op = (float4*)(out + (size_t)pos * DIM);
    op[lane]      = o0;   // dims [4*lane, 4*lane+4)
    op[32 + lane] = o1;   // dims [128+4*lane, ...)
}

extern "C" void kernel_launch(void* const* d_in, const int* in_sizes, int n_in,
                              void* d_out, int out_size) {
    const int*   ids   = (const int*)d_in[0];     // [32,128,32] int32
    const float* table = (const float*)d_in[1];   // [32000,256] f32
    const float* gamma = (const float*)d_in[2];   // [256]
    const float* beta  = (const float*)d_in[3];   // [256]
    float* out = (float*)d_out;                   // [32,128,256] f32

    const int n_pos = in_sizes[0] / WORDS;        // 4096
    emb_ln_sum_kernel<<<n_pos / WPB, 32 * WPB>>>(ids, table, gamma, beta, out);
}

// round 11
// speedup vs baseline: 1.3681x; 1.3681x over previous
#include <cuda_runtime.h>
#include <cstdint>

// TextEmbedding: gather [B,S,W,D] from table, per-token LayerNorm, sum over W.
// B=32, S=128, W=32, D=256  -> out [B*S, D] f32.
//
// R11 = R8's contiguous cp.async producer (each LDGSTS = 512B contiguous
// across the warp; THE thing R10 broke) + R10's leaner reduction tail
// (xor16 exchange of rstd/msh instead of fold+2 broadcasts) + 4-stage ring
// at prefetch distance 3 + 2-warp CTAs (low wave quantization).

#define DIM 256
#define WORDS 32
#define EPS 1e-12f
#define STAGES 4
#define NCHUNK 16           // 2 words per chunk
#define WPB 2               // warps per block

typedef unsigned long long u64;

__device__ __forceinline__ u64 pack2(float lo, float hi) {
    u64 r; asm("mov.b64 %0, {%1, %2};" : "=l"(r) : "f"(lo), "f"(hi)); return r;
}
__device__ __forceinline__ void unpack2(u64 v, float& lo, float& hi) {
    asm("mov.b64 {%0, %1}, %2;" : "=f"(lo), "=f"(hi) : "l"(v));
}
__device__ __forceinline__ u64 add2(u64 a, u64 b) {
    u64 d; asm("add.rn.f32x2 %0, %1, %2;" : "=l"(d) : "l"(a), "l"(b)); return d;
}
__device__ __forceinline__ u64 mul2(u64 a, u64 b) {
    u64 d; asm("mul.rn.f32x2 %0, %1, %2;" : "=l"(d) : "l"(a), "l"(b)); return d;
}
__device__ __forceinline__ u64 fma2(u64 a, u64 b, u64 c) {
    u64 d; asm("fma.rn.f32x2 %0, %1, %2, %3;" : "=l"(d) : "l"(a), "l"(b), "l"(c)); return d;
}

__device__ __forceinline__ void cp16(uint32_t dst_smem, const void* src) {
    asm volatile("cp.async.cg.shared.global [%0], [%1], 16;"
                 :: "r"(dst_smem), "l"(src));
}
__device__ __forceinline__ void cp_commit() {
    asm volatile("cp.async.commit_group;");
}
template <int N> __device__ __forceinline__ void cp_wait() {
    asm volatile("cp.async.wait_group %0;" :: "n"(N));
}

__global__ __launch_bounds__(64)
void emb_ln_sum_kernel(const int* __restrict__ ids,
                       const float* __restrict__ table,
                       const float* __restrict__ gamma,
                       const float* __restrict__ beta,
                       float* __restrict__ out) {
    // [warp][stage][slot][lane] : slot = {w0.lo, w0.hi, w1.lo, w1.hi}
    __shared__ float4 buf[WPB][STAGES][4][32];

    const int tid  = threadIdx.x;
    const int warp = tid >> 5;
    const int lane = tid & 31;
    const int pos  = blockIdx.x * WPB + warp;   // 0..4095

    // Lane L holds id of word L (one coalesced LDG.32 per warp).
    const int id_lane = __ldg(ids + pos * WORDS + lane);

    const uint32_t sbase =
        (uint32_t)__cvta_generic_to_shared(&buf[warp][0][0][lane]);
    const uint32_t stage_stride = 4 * 32 * sizeof(float4);  // 2048 B
    const uint32_t slot_stride  = 32 * sizeof(float4);      // 512 B

    // Producer: chunk c (words 2c, 2c+1); each cp16 is 512B contiguous
    // across the warp (lane address = row + 4*lane floats).
    auto issue = [&](int c) {
        const int id0 = __shfl_sync(0xffffffffu, id_lane, 2 * c);
        const int id1 = __shfl_sync(0xffffffffu, id_lane, 2 * c + 1);
        const float* r0 = table + (size_t)id0 * DIM + 4 * lane;
        const float* r1 = table + (size_t)id1 * DIM + 4 * lane;
        const uint32_t s = sbase + (uint32_t)(c & (STAGES - 1)) * stage_stride;
        cp16(s,                   r0);
        cp16(s + slot_stride,     r0 + 128);
        cp16(s + 2 * slot_stride, r1);
        cp16(s + 3 * slot_stride, r1 + 128);
        cp_commit();
    };

    u64 acc[4];
    const u64 z = pack2(0.0f, 0.0f);
    acc[0] = z; acc[1] = z; acc[2] = z; acc[3] = z;
    float mtot = 0.0f;

    issue(0); issue(1); issue(2);

    #pragma unroll
    for (int c = 0; c < NCHUNK; c++) {
        if (c + 3 < NCHUNK) { issue(c + 3); cp_wait<3>(); }
        else if (c + 2 < NCHUNK) cp_wait<2>();
        else if (c + 1 < NCHUNK) cp_wait<1>();
        else                     cp_wait<0>();

        // Lane reads back its own dims (conflict-free LDS.128).
        const float4* sp = &buf[warp][c & (STAGES - 1)][0][lane];
        const float4 R0 = sp[0];    // word0 dims [4L, 4L+4)
        const float4 R1 = sp[32];   // word0 dims [128+4L, ...)
        const float4 R2 = sp[64];   // word1 low
        const float4 R3 = sp[96];   // word1 high

        // Per-lane partials: v = {s0, q0, s1, q1}
        float v[4];
        {
            const u64 a01 = pack2(R0.x, R0.y), a23 = pack2(R0.z, R0.w);
            const u64 b01 = pack2(R1.x, R1.y), b23 = pack2(R1.z, R1.w);
            const u64 s2 = add2(add2(a01, a23), add2(b01, b23));
            const u64 q2 = fma2(a01, a01, fma2(a23, a23, fma2(b01, b01, mul2(b23, b23))));
            float sl, sh, ql, qh;
            unpack2(s2, sl, sh); unpack2(q2, ql, qh);
            v[0] = sl + sh; v[1] = ql + qh;
        }
        {
            const u64 a01 = pack2(R2.x, R2.y), a23 = pack2(R2.z, R2.w);
            const u64 b01 = pack2(R3.x, R3.y), b23 = pack2(R3.z, R3.w);
            const u64 s2 = add2(add2(a01, a23), add2(b01, b23));
            const u64 q2 = fma2(a01, a01, fma2(a23, a23, fma2(b01, b01, mul2(b23, b23))));
            float sl, sh, ql, qh;
            unpack2(s2, sl, sh); unpack2(q2, ql, qh);
            v[2] = sl + sh; v[3] = ql + qh;
        }

        // Fold: bit16 selects word, bit8 selects s/q; butterfly 4,2,1.
        const bool hi16 = (lane & 16) != 0;
        float w2[2];
        #pragma unroll
        for (int j = 0; j < 2; j++) {
            float send = hi16 ? v[j] : v[j + 2];
            float keep = hi16 ? v[j + 2] : v[j];
            w2[j] = keep + __shfl_xor_sync(0xffffffffu, send, 16);
        }
        const bool hi8 = (lane & 8) != 0;
        float y;
        {
            float send = hi8 ? w2[0] : w2[1];
            float keep = hi8 ? w2[1] : w2[0];
            y = keep + __shfl_xor_sync(0xffffffffu, send, 8);
        }
        y += __shfl_xor_sync(0xffffffffu, y, 4);
        y += __shfl_xor_sync(0xffffffffu, y, 2);
        y += __shfl_xor_sync(0xffffffffu, y, 1);
        // Lane holds: (s or q, by b8) of word b16.

        const float p  = __shfl_xor_sync(0xffffffffu, y, 8);
        const float s_ = hi8 ? p : y;
        const float q_ = hi8 ? y : p;
        const float mu  = s_ * (1.0f / 256.0f);
        const float var = q_ * (1.0f / 256.0f) - mu * mu;
        const float r_  = rsqrtf(var + EPS);
        const float msh = -mu * r_;

        // Exchange (rstd, msh) with the other word's lanes (leaner tail).
        const float r_o   = __shfl_xor_sync(0xffffffffu, r_, 16);
        const float msh_o = __shfl_xor_sync(0xffffffffu, msh, 16);
        mtot += msh + msh_o;
        const float r0 = hi16 ? r_o : r_;
        const float r1 = hi16 ? r_ : r_o;

        const u64 rr0 = pack2(r0, r0);
        const u64 rr1 = pack2(r1, r1);
        acc[0] = fma2(pack2(R0.x, R0.y), rr0, acc[0]);
        acc[1] = fma2(pack2(R0.z, R0.w), rr0, acc[1]);
        acc[2] = fma2(pack2(R1.x, R1.y), rr0, acc[2]);
        acc[3] = fma2(pack2(R1.z, R1.w), rr0, acc[3]);
        acc[0] = fma2(pack2(R2.x, R2.y), rr1, acc[0]);
        acc[1] = fma2(pack2(R2.z, R2.w), rr1, acc[1]);
        acc[2] = fma2(pack2(R3.x, R3.y), rr1, acc[2]);
        acc[3] = fma2(pack2(R3.z, R3.w), rr1, acc[3]);
    }

    // out = (acc + mtot) * gamma + 32 * beta, per lane dims.
    float a0, a1, a2, a3, a4, a5, a6, a7;
    unpack2(acc[0], a0, a1); unpack2(acc[1], a2, a3);
    unpack2(acc[2], a4, a5); unpack2(acc[3], a6, a7);

    const float4 g0  = __ldg((const float4*)gamma + lane);
    const float4 g1  = __ldg((const float4*)gamma + 32 + lane);
    const float4 bt0 = __ldg((const float4*)beta + lane);
    const float4 bt1 = __ldg((const float4*)beta + 32 + lane);

    float4 o0, o1;
    o0.x = fmaf(a0 + mtot, g0.x, 32.0f * bt0.x);
    o0.y = fmaf(a1 + mtot, g0.y, 32.0f * bt0.y);
    o0.z = fmaf(a2 + mtot, g0.z, 32.0f * bt0.z);
    o0.w = fmaf(a3 + mtot, g0.w, 32.0f * bt0.w);
    o1.x = fmaf(a4 + mtot, g1.x, 32.0f * bt1.x);
    o1.y = fmaf(a5 + mtot, g1.y, 32.0f * bt1.y);
    o1.z = fmaf(a6 + mtot, g1.z, 32.0f * bt1.z);
    o1.w = fmaf(a7 + mtot, g1.w, 32.0f * bt1.w);

    float4* op = (float4*)(out + (size_t)pos * DIM);
    op[lane]      = o0;   // dims [4*lane, 4*lane+4)
    op[32 + lane] = o1;   // dims [128+4*lane, ...)
}

extern "C" void kernel_launch(void* const* d_in, const int* in_sizes, int n_in,
                              void* d_out, int out_size) {
    const int*   ids   = (const int*)d_in[0];     // [32,128,32] int32
    const float* table = (const float*)d_in[1];   // [32000,256] f32
    const float* gamma = (const float*)d_in[2];   // [256]
    const float* beta  = (const float*)d_in[3];   // [256]
    float* out = (float*)d_out;                   // [32,128,256] f32

    const int n_pos = in_sizes[0] / WORDS;        // 4096
    emb_ln_sum_kernel<<<n_pos / WPB, 32 * WPB>>>(ids, table, gamma, beta, out);
}

// round 12
// speedup vs baseline: 1.5275x; 1.1165x over previous
#include <cuda_runtime.h>
#include <cstdint>

// TextEmbedding: gather [B,S,W,D] from table, per-token LayerNorm, sum over W.
// B=32, S=128, W=32, D=256  -> out [B*S, D] f32.
//
// R12 = R8 verbatim (contiguous cp.async producer, 2 words/chunk, R8's
// reduction tail, regs ~56) with exactly two config changes:
//   WPB=4 (block 128, grid 1024): CTA wave imbalance 33% -> 14%.
//   STAGES=4, prefetch distance 3: deeper cover of L2 latency.

#define DIM 256
#define WORDS 32
#define EPS 1e-12f
#define STAGES 4
#define NCHUNK 16           // 2 words per chunk
#define WPB 4               // warps per block

typedef unsigned long long u64;

__device__ __forceinline__ u64 pack2(float lo, float hi) {
    u64 r; asm("mov.b64 %0, {%1, %2};" : "=l"(r) : "f"(lo), "f"(hi)); return r;
}
__device__ __forceinline__ void unpack2(u64 v, float& lo, float& hi) {
    asm("mov.b64 {%0, %1}, %2;" : "=f"(lo), "=f"(hi) : "l"(v));
}
__device__ __forceinline__ u64 add2(u64 a, u64 b) {
    u64 d; asm("add.rn.f32x2 %0, %1, %2;" : "=l"(d) : "l"(a), "l"(b)); return d;
}
__device__ __forceinline__ u64 mul2(u64 a, u64 b) {
    u64 d; asm("mul.rn.f32x2 %0, %1, %2;" : "=l"(d) : "l"(a), "l"(b)); return d;
}
__device__ __forceinline__ u64 fma2(u64 a, u64 b, u64 c) {
    u64 d; asm("fma.rn.f32x2 %0, %1, %2, %3;" : "=l"(d) : "l"(a), "l"(b), "l"(c)); return d;
}

__device__ __forceinline__ void cp16(uint32_t dst_smem, const void* src) {
    asm volatile("cp.async.cg.shared.global [%0], [%1], 16;"
                 :: "r"(dst_smem), "l"(src));
}
__device__ __forceinline__ void cp_commit() {
    asm volatile("cp.async.commit_group;");
}
template <int N> __device__ __forceinline__ void cp_wait() {
    asm volatile("cp.async.wait_group %0;" :: "n"(N));
}

__global__ __launch_bounds__(32 * WPB)
void emb_ln_sum_kernel(const int* __restrict__ ids,
                       const float* __restrict__ table,
                       const float* __restrict__ gamma,
                       const float* __restrict__ beta,
                       float* __restrict__ out) {
    // [warp][stage][slot][lane] : slot = {w0.lo, w0.hi, w1.lo, w1.hi}
    __shared__ float4 buf[WPB][STAGES][4][32];

    const int tid  = threadIdx.x;
    const int warp = tid >> 5;
    const int lane = tid & 31;
    const int pos  = blockIdx.x * WPB + warp;   // 0..4095

    // Lane L holds id of word L (one coalesced LDG.32 per warp).
    const int id_lane = __ldg(ids + pos * WORDS + lane);

    const uint32_t sbase =
        (uint32_t)__cvta_generic_to_shared(&buf[warp][0][0][lane]);
    const uint32_t stage_stride = 4 * 32 * sizeof(float4);  // 2048 B
    const uint32_t slot_stride  = 32 * sizeof(float4);      // 512 B

    // Producer: chunk c (words 2c, 2c+1); each cp16 is 512B contiguous
    // across the warp (lane address = row + 4*lane floats).
    auto issue = [&](int c) {
        const int id0 = __shfl_sync(0xffffffffu, id_lane, 2 * c);
        const int id1 = __shfl_sync(0xffffffffu, id_lane, 2 * c + 1);
        const float* r0 = table + (size_t)id0 * DIM + 4 * lane;
        const float* r1 = table + (size_t)id1 * DIM + 4 * lane;
        const uint32_t s = sbase + (uint32_t)(c & (STAGES - 1)) * stage_stride;
        cp16(s,                   r0);
        cp16(s + slot_stride,     r0 + 128);
        cp16(s + 2 * slot_stride, r1);
        cp16(s + 3 * slot_stride, r1 + 128);
        cp_commit();
    };

    u64 acc[4];
    const u64 z = pack2(0.0f, 0.0f);
    acc[0] = z; acc[1] = z; acc[2] = z; acc[3] = z;
    float mtot = 0.0f;

    issue(0); issue(1); issue(2);

    #pragma unroll
    for (int c = 0; c < NCHUNK; c++) {
        if (c + 3 < NCHUNK) { issue(c + 3); cp_wait<3>(); }
        else if (c + 2 < NCHUNK) cp_wait<2>();
        else if (c + 1 < NCHUNK) cp_wait<1>();
        else                     cp_wait<0>();

        // Lane reads back its own dims (conflict-free LDS.128).
        const float4* sp = &buf[warp][c & (STAGES - 1)][0][lane];
        const float4 R0 = sp[0];    // word0 dims [4L, 4L+4)
        const float4 R1 = sp[32];   // word0 dims [128+4L, ...)
        const float4 R2 = sp[64];   // word1 low
        const float4 R3 = sp[96];   // word1 high

        // Per-lane partials: v = {s0, q0, s1, q1}
        float v[4];
        {
            const u64 a01 = pack2(R0.x, R0.y), a23 = pack2(R0.z, R0.w);
            const u64 b01 = pack2(R1.x, R1.y), b23 = pack2(R1.z, R1.w);
            const u64 s2 = add2(add2(a01, a23), add2(b01, b23));
            const u64 q2 = fma2(a01, a01, fma2(a23, a23, fma2(b01, b01, mul2(b23, b23))));
            float sl, sh, ql, qh;
            unpack2(s2, sl, sh); unpack2(q2, ql, qh);
            v[0] = sl + sh; v[1] = ql + qh;
        }
        {
            const u64 a01 = pack2(R2.x, R2.y), a23 = pack2(R2.z, R2.w);
            const u64 b01 = pack2(R3.x, R3.y), b23 = pack2(R3.z, R3.w);
            const u64 s2 = add2(add2(a01, a23), add2(b01, b23));
            const u64 q2 = fma2(a01, a01, fma2(a23, a23, fma2(b01, b01, mul2(b23, b23))));
            float sl, sh, ql, qh;
            unpack2(s2, sl, sh); unpack2(q2, ql, qh);
            v[2] = sl + sh; v[3] = ql + qh;
        }

        // Fold: bit16 selects word, bit8 selects s/q; butterfly 4,2,1.
        const bool hi16 = (lane & 16) != 0;
        float w2[2];
        #pragma unroll
        for (int j = 0; j < 2; j++) {
            float send = hi16 ? v[j] : v[j + 2];
            float keep = hi16 ? v[j + 2] : v[j];
            w2[j] = keep + __shfl_xor_sync(0xffffffffu, send, 16);
        }
        const bool hi8 = (lane & 8) != 0;
        float y;
        {
            float send = hi8 ? w2[0] : w2[1];
            float keep = hi8 ? w2[1] : w2[0];
            y = keep + __shfl_xor_sync(0xffffffffu, send, 8);
        }
        y += __shfl_xor_sync(0xffffffffu, y, 4);
        y += __shfl_xor_sync(0xffffffffu, y, 2);
        y += __shfl_xor_sync(0xffffffffu, y, 1);
        // Lane holds: word W = b16; b8 = 0 -> s_W, b8 = 1 -> q_W.

        const float p  = __shfl_xor_sync(0xffffffffu, y, 8);
        const float s_ = hi8 ? p : y;
        const float q_ = hi8 ? y : p;
        const float mu  = s_ * (1.0f / 256.0f);
        const float var = q_ * (1.0f / 256.0f) - mu * mu;
        const float r_  = rsqrtf(var + EPS);
        const float msh = -mu * r_;

        mtot += msh + __shfl_xor_sync(0xffffffffu, msh, 16);

        const float r0 = __shfl_sync(0xffffffffu, r_, 0);
        const float r1 = __shfl_sync(0xffffffffu, r_, 16);
        const u64 rr0 = pack2(r0, r0);
        const u64 rr1 = pack2(r1, r1);
        acc[0] = fma2(pack2(R0.x, R0.y), rr0, acc[0]);
        acc[1] = fma2(pack2(R0.z, R0.w), rr0, acc[1]);
        acc[2] = fma2(pack2(R1.x, R1.y), rr0, acc[2]);
        acc[3] = fma2(pack2(R1.z, R1.w), rr0, acc[3]);
        acc[0] = fma2(pack2(R2.x, R2.y), rr1, acc[0]);
        acc[1] = fma2(pack2(R2.z, R2.w), rr1, acc[1]);
        acc[2] = fma2(pack2(R3.x, R3.y), rr1, acc[2]);
        acc[3] = fma2(pack2(R3.z, R3.w), rr1, acc[3]);
    }

    // out = (acc + mtot) * gamma + 32 * beta, per lane dims.
    float a0, a1, a2, a3, a4, a5, a6, a7;
    unpack2(acc[0], a0, a1); unpack2(acc[1], a2, a3);
    unpack2(acc[2], a4, a5); unpack2(acc[3], a6, a7);

    const float4 g0  = __ldg((const float4*)gamma + lane);
    const float4 g1  = __ldg((const float4*)gamma + 32 + lane);
    const float4 bt0 = __ldg((const float4*)beta + lane);
    const float4 bt1 = __ldg((const float4*)beta + 32 + lane);

    float4 o0, o1;
    o0.x = fmaf(a0 + mtot, g0.x, 32.0f * bt0.x);
    o0.y = fmaf(a1 + mtot, g0.y, 32.0f * bt0.y);
    o0.z = fmaf(a2 + mtot, g0.z, 32.0f * bt0.z);
    o0.w = fmaf(a3 + mtot, g0.w, 32.0f * bt0.w);
    o1.x = fmaf(a4 + mtot, g1.x, 32.0f * bt1.x);
    o1.y = fmaf(a5 + mtot, g1.y, 32.0f * bt1.y);
    o1.z = fmaf(a6 + mtot, g1.z, 32.0f * bt1.z);
    o1.w = fmaf(a7 + mtot, g1.w, 32.0f * bt1.w);

    float4* op = (float4*)(out + (size_t)pos * DIM);
    op[lane]      = o0;   // dims [4*lane, 4*lane+4)
    op[32 + lane] = o1;   // dims [128+4*lane, ...)
}

extern "C" void kernel_launch(void* const* d_in, const int* in_sizes, int n_in,
                              void* d_out, int out_size) {
    const int*   ids   = (const int*)d_in[0];     // [32,128,32] int32
    const float* table = (const float*)d_in[1];   // [32000,256] f32
    const float* gamma = (const float*)d_in[2];   // [256]
    const float* beta  = (const float*)d_in[3];   // [256]
    float* out = (float*)d_out;                   // [32,128,256] f32

    const int n_pos = in_sizes[0] / WORDS;        // 4096
    emb_ln_sum_kernel<<<n_pos / WPB, 32 * WPB>>>(ids, table, gamma, beta, out);
}

// round 13
// speedup vs baseline: 1.5539x; 1.0172x over previous
#include <cuda_runtime.h>
#include <cstdint>

// TextEmbedding: gather [B,S,W,D] from table, per-token LayerNorm, sum over W.
// B=32, S=128, W=32, D=256  -> out [B*S, D] f32.
//
// R13 = R8 verbatim (contiguous cp.async producer, 3-stage ring, distance 2,
// R8's reduction tail -> regs ~56-64) with ONLY WPB changed 8 -> 4:
// grid 1024 = 6.9 CTAs/SM, last-wave imbalance 33% -> 14%.
// We are at the L2 random-gather bandwidth cap (~9.3 TB/s); this targets the
// only remaining slack (wave tail).

#define DIM 256
#define WORDS 32
#define EPS 1e-12f
#define STAGES 3
#define NCHUNK 16           // 2 words per chunk
#define WPB 4               // warps per block

typedef unsigned long long u64;

__device__ __forceinline__ u64 pack2(float lo, float hi) {
    u64 r; asm("mov.b64 %0, {%1, %2};" : "=l"(r) : "f"(lo), "f"(hi)); return r;
}
__device__ __forceinline__ void unpack2(u64 v, float& lo, float& hi) {
    asm("mov.b64 {%0, %1}, %2;" : "=f"(lo), "=f"(hi) : "l"(v));
}
__device__ __forceinline__ u64 add2(u64 a, u64 b) {
    u64 d; asm("add.rn.f32x2 %0, %1, %2;" : "=l"(d) : "l"(a), "l"(b)); return d;
}
__device__ __forceinline__ u64 mul2(u64 a, u64 b) {
    u64 d; asm("mul.rn.f32x2 %0, %1, %2;" : "=l"(d) : "l"(a), "l"(b)); return d;
}
__device__ __forceinline__ u64 fma2(u64 a, u64 b, u64 c) {
    u64 d; asm("fma.rn.f32x2 %0, %1, %2, %3;" : "=l"(d) : "l"(a), "l"(b), "l"(c)); return d;
}

__device__ __forceinline__ void cp16(uint32_t dst_smem, const void* src) {
    asm volatile("cp.async.cg.shared.global [%0], [%1], 16;"
                 :: "r"(dst_smem), "l"(src));
}
__device__ __forceinline__ void cp_commit() {
    asm volatile("cp.async.commit_group;");
}
template <int N> __device__ __forceinline__ void cp_wait() {
    asm volatile("cp.async.wait_group %0;" :: "n"(N));
}

__global__ __launch_bounds__(32 * WPB)
void emb_ln_sum_kernel(const int* __restrict__ ids,
                       const float* __restrict__ table,
                       const float* __restrict__ gamma,
                       const float* __restrict__ beta,
                       float* __restrict__ out) {
    // [warp][stage][slot][lane] : slot = {w0.lo, w0.hi, w1.lo, w1.hi}
    __shared__ float4 buf[WPB][STAGES][4][32];

    const int tid  = threadIdx.x;
    const int warp = tid >> 5;
    const int lane = tid & 31;
    const int pos  = blockIdx.x * WPB + warp;   // 0..4095

    // Lane L holds id of word L (one coalesced LDG.32 per warp).
    const int id_lane = __ldg(ids + pos * WORDS + lane);

    const uint32_t sbase =
        (uint32_t)__cvta_generic_to_shared(&buf[warp][0][0][lane]);
    const uint32_t stage_stride = 4 * 32 * sizeof(float4);  // 2048 B
    const uint32_t slot_stride  = 32 * sizeof(float4);      // 512 B

    // Producer: chunk c (words 2c, 2c+1); each cp16 is 512B contiguous
    // across the warp (lane address = row + 4*lane floats).
    auto issue = [&](int c) {
        const int id0 = __shfl_sync(0xffffffffu, id_lane, 2 * c);
        const int id1 = __shfl_sync(0xffffffffu, id_lane, 2 * c + 1);
        const float* r0 = table + (size_t)id0 * DIM + 4 * lane;
        const float* r1 = table + (size_t)id1 * DIM + 4 * lane;
        const uint32_t s = sbase + (uint32_t)(c % STAGES) * stage_stride;
        cp16(s,                   r0);
        cp16(s + slot_stride,     r0 + 128);
        cp16(s + 2 * slot_stride, r1);
        cp16(s + 3 * slot_stride, r1 + 128);
        cp_commit();
    };

    u64 acc[4];
    const u64 z = pack2(0.0f, 0.0f);
    acc[0] = z; acc[1] = z; acc[2] = z; acc[3] = z;
    float mtot = 0.0f;

    issue(0);
    issue(1);

    #pragma unroll
    for (int c = 0; c < NCHUNK; c++) {
        if (c + 2 < NCHUNK) issue(c + 2);

        // Wait until chunk c's group has landed.
        if (c + 2 < NCHUNK)      cp_wait<2>();
        else if (c + 1 < NCHUNK) cp_wait<1>();
        else                     cp_wait<0>();

        // Read this lane's own bytes back from smem (conflict-free LDS.128).
        const float4* sp = &buf[warp][c % STAGES][0][lane];
        const float4 R0 = sp[0];
        const float4 R1 = sp[32];
        const float4 R2 = sp[64];
        const float4 R3 = sp[96];

        // Per-lane partials: v = {s0, q0, s1, q1}
        float v[4];
        {
            const u64 a01 = pack2(R0.x, R0.y), a23 = pack2(R0.z, R0.w);
            const u64 b01 = pack2(R1.x, R1.y), b23 = pack2(R1.z, R1.w);
            const u64 s2 = add2(add2(a01, a23), add2(b01, b23));
            const u64 q2 = fma2(a01, a01, fma2(a23, a23, fma2(b01, b01, mul2(b23, b23))));
            float sl, sh, ql, qh;
            unpack2(s2, sl, sh); unpack2(q2, ql, qh);
            v[0] = sl + sh; v[1] = ql + qh;
        }
        {
            const u64 a01 = pack2(R2.x, R2.y), a23 = pack2(R2.z, R2.w);
            const u64 b01 = pack2(R3.x, R3.y), b23 = pack2(R3.z, R3.w);
            const u64 s2 = add2(add2(a01, a23), add2(b01, b23));
            const u64 q2 = fma2(a01, a01, fma2(a23, a23, fma2(b01, b01, mul2(b23, b23))));
            float sl, sh, ql, qh;
            unpack2(s2, sl, sh); unpack2(q2, ql, qh);
            v[2] = sl + sh; v[3] = ql + qh;
        }

        // Fold: bit16 selects word, bit8 selects s/q; butterfly 4,2,1.
        const bool hi16 = (lane & 16) != 0;
        float w2[2];
        #pragma unroll
        for (int j = 0; j < 2; j++) {
            float send = hi16 ? v[j] : v[j + 2];
            float keep = hi16 ? v[j + 2] : v[j];
            w2[j] = keep + __shfl_xor_sync(0xffffffffu, send, 16);
        }
        const bool hi8 = (lane & 8) != 0;
        float y;
        {
            float send = hi8 ? w2[0] : w2[1];
            float keep = hi8 ? w2[1] : w2[0];
            y = keep + __shfl_xor_sync(0xffffffffu, send, 8);
        }
        y += __shfl_xor_sync(0xffffffffu, y, 4);
        y += __shfl_xor_sync(0xffffffffu, y, 2);
        y += __shfl_xor_sync(0xffffffffu, y, 1);
        // Lane holds: word W = b16; b8 = 0 -> s_W, b8 = 1 -> q_W.

        const float p  = __shfl_xor_sync(0xffffffffu, y, 8);
        const float s_ = hi8 ? p : y;
        const float q_ = hi8 ? y : p;
        const float mu  = s_ * (1.0f / 256.0f);
        const float var = q_ * (1.0f / 256.0f) - mu * mu;
        const float r_  = rsqrtf(var + EPS);
        const float msh = -mu * r_;

        mtot += msh + __shfl_xor_sync(0xffffffffu, msh, 16);

        const float r0 = __shfl_sync(0xffffffffu, r_, 0);
        const float r1 = __shfl_sync(0xffffffffu, r_, 16);
        const u64 rr0 = pack2(r0, r0);
        const u64 rr1 = pack2(r1, r1);
        acc[0] = fma2(pack2(R0.x, R0.y), rr0, acc[0]);
        acc[1] = fma2(pack2(R0.z, R0.w), rr0, acc[1]);
        acc[2] = fma2(pack2(R1.x, R1.y), rr0, acc[2]);
        acc[3] = fma2(pack2(R1.z, R1.w), rr0, acc[3]);
        acc[0] = fma2(pack2(R2.x, R2.y), rr1, acc[0]);
        acc[1] = fma2(pack2(R2.z, R2.w), rr1, acc[1]);
        acc[2] = fma2(pack2(R3.x, R3.y), rr1, acc[2]);
        acc[3] = fma2(pack2(R3.z, R3.w), rr1, acc[3]);
    }

    // out = (acc + mtot) * gamma + 32 * beta, per lane dims.
    float a0, a1, a2, a3, a4, a5, a6, a7;
    unpack2(acc[0], a0, a1); unpack2(acc[1], a2, a3);
    unpack2(acc[2], a4, a5); unpack2(acc[3], a6, a7);

    const float4 g0  = __ldg((const float4*)gamma + lane);
    const float4 g1  = __ldg((const float4*)gamma + 32 + lane);
    const float4 bt0 = __ldg((const float4*)beta + lane);
    const float4 bt1 = __ldg((const float4*)beta + 32 + lane);

    float4 o0, o1;
    o0.x = fmaf(a0 + mtot, g0.x, 32.0f * bt0.x);
    o0.y = fmaf(a1 + mtot, g0.y, 32.0f * bt0.y);
    o0.z = fmaf(a2 + mtot, g0.z, 32.0f * bt0.z);
    o0.w = fmaf(a3 + mtot, g0.w, 32.0f * bt0.w);
    o1.x = fmaf(a4 + mtot, g1.x, 32.0f * bt1.x);
    o1.y = fmaf(a5 + mtot, g1.y, 32.0f * bt1.y);
    o1.z = fmaf(a6 + mtot, g1.z, 32.0f * bt1.z);
    o1.w = fmaf(a7 + mtot, g1.w, 32.0f * bt1.w);

    float4* op = (float4*)(out + (size_t)pos * DIM);
    op[lane]      = o0;   // dims [4*lane, 4*lane+4)
    op[32 + lane] = o1;   // dims [128+4*lane, ...)
}

extern "C" void kernel_launch(void* const* d_in, const int* in_sizes, int n_in,
                              void* d_out, int out_size) {
    const int*   ids   = (const int*)d_in[0];     // [32,128,32] int32
    const float* table = (const float*)d_in[1];   // [32000,256] f32
    const float* gamma = (const float*)d_in[2];   // [256]
    const float* beta  = (const float*)d_in[3];   // [256]
    float* out = (float*)d_out;                   // [32,128,256] f32

    const int n_pos = in_sizes[0] / WORDS;        // 4096
    emb_ln_sum_kernel<<<n_pos / WPB, 32 * WPB>>>(ids, table, gamma, beta, out);
}